// round 15
// baseline (speedup 1.0000x reference)
#include <cuda_runtime.h>
#include <cuda_fp16.h>
#include <cstdint>
#include <cstddef>

#define NN   50000
#define NE   800000
#define DIN  256
#define DHID 256
#define DOUT 128
#define MID  25088    // gather_h/gemm2 split point (multiple of 128)

#define SCAN_B 256
#define SCAN_GRID ((NN + SCAN_B - 1) / SCAN_B)   // 196

// ---------------- scratch (device globals; no allocation allowed) ----------------
// g_outc/g_inc rely on zero-initialization at module load; every call re-zeroes
// them at its tail (shadowed), so each invocation starts from zeros.
__device__ float g_outnorm[NN];
__device__ float g_innorm[NN];
__device__ int   g_outc[NN];
__device__ int   g_inc[NN];
__device__ int   g_rowptr[NN + 1];
__device__ int   g_cursor[NN];
__device__ int   g_poff[SCAN_B];                 // per-block inc sums
__device__ int   g_csrc[NE];                     // src node per CSR slot (by dst)
__device__ __half g_th[(size_t)NN * DHID];       // pre-agg features t (fp16)
__device__ __half g_hh[(size_t)NN * DHID];       // fp16 copy of h (gemm2 input)
__device__ __half g_fh[(size_t)NN * DIN];        // fp16 features
__device__ __half g_w1h[DIN * DHID];             // W1^T  [n][k] fp16
__device__ __half g_w23h[DHID * DHID];           // [W2|W3]^T [n][k] fp16
__device__ __half g_fcwh[DHID * DIN];            // fcW (already [n][k]) fp16

// ---------------- unified conversion kernel ----------------
// threads [0, NN*DIN/4): features (float4 -> half2x2)
// then 65536 W1-transpose, 65536 fcW-direct, 65536 W2|W3-transpose
#define CONV_FEAT_T (NN * (DIN / 4))             // 3,200,000
#define CONV_TOTAL  (CONV_FEAT_T + 3 * 65536)

__global__ void k_conv_all(const float* __restrict__ f,
                           const float* __restrict__ W1, const float* __restrict__ W2,
                           const float* __restrict__ W3, const float* __restrict__ fcW) {
    int t = blockIdx.x * blockDim.x + threadIdx.x;
    if (t < CONV_FEAT_T) {
        float4 v = ((const float4*)f)[t];
        __half2 h0 = __float22half2_rn(make_float2(v.x, v.y));
        __half2 h1 = __float22half2_rn(make_float2(v.z, v.w));
        uint2 o;
        o.x = *(uint32_t*)&h0;
        o.y = *(uint32_t*)&h1;
        ((uint2*)g_fh)[t] = o;
        return;
    }
    int w = t - CONV_FEAT_T;
    if (w < 65536) {                              // W1 -> g_w1h transposed
        int n = w >> 8, k = w & 255;
        g_w1h[w] = __float2half(W1[k * 256 + n]);
    } else if (w < 131072) {                      // fcW -> g_fcwh direct
        int i = w - 65536;
        g_fcwh[i] = __float2half(fcW[i]);
    } else if (w < 196608) {                      // W2|W3 -> g_w23h transposed
        int i = w - 131072;
        int hs = i >> 15;
        int j = i & 32767;
        int n = j >> 8, k = j & 255;
        const float* S = hs ? W3 : W2;
        g_w23h[(size_t)(hs * 128 + n) * 256 + k] = __float2half(S[k * 128 + n]);
    }
}

// ---------------- degree / norm / CSR kernels ----------------
// 2 edges per thread
__global__ void k_degree(const int* __restrict__ src, const int* __restrict__ dst) {
    int e = (blockIdx.x * blockDim.x + threadIdx.x) * 2;
    if (e + 1 < NE) {
        int2 s = *(const int2*)(src + e);
        int2 d = *(const int2*)(dst + e);
        atomicAdd(&g_outc[s.x], 1);
        atomicAdd(&g_outc[s.y], 1);
        atomicAdd(&g_inc[d.x], 1);
        atomicAdd(&g_inc[d.y], 1);
    } else if (e < NE) {
        atomicAdd(&g_outc[src[e]], 1);
        atomicAdd(&g_inc[dst[e]], 1);
    }
}

// tail zeroing (runs shadowed at graph end; restores zero-state for next replay)
__global__ void k_zero_counts() {
    int i = blockIdx.x * blockDim.x + threadIdx.x;
    if (i < NN) { g_outc[i] = 0; g_inc[i] = 0; }
}

// phase 1 (fused with norms): per-block inc sums + out/in norms
__global__ void k_scan_p1n() {
    __shared__ int ws[8];
    int i = blockIdx.x * SCAN_B + threadIdx.x;
    int lane = threadIdx.x & 31, wid = threadIdx.x >> 5;
    int v = 0;
    if (i < NN) {
        int oc = g_outc[i];
        v = g_inc[i];
        g_outnorm[i] = rsqrtf(fmaxf((float)oc, 1.f));
        g_innorm[i]  = rsqrtf(fmaxf((float)v, 1.f));
    }
    int x = v;
#pragma unroll
    for (int o = 16; o > 0; o >>= 1) x += __shfl_down_sync(0xffffffffu, x, o);
    if (lane == 0) ws[wid] = x;
    __syncthreads();
    if (wid == 0) {
        int s = (lane < 8) ? ws[lane] : 0;
#pragma unroll
        for (int o = 4; o > 0; o >>= 1) s += __shfl_down_sync(0xffffffffu, s, o);
        if (lane == 0) g_poff[blockIdx.x] = s;
    }
}

// phase 2+3 fused: each block reduces g_poff[0..b) itself, then local scan.
__global__ void k_scan_p3f() {
    __shared__ int ws[8];
    __shared__ int s_off;
    const int b = blockIdx.x;
    int tid = threadIdx.x, lane = tid & 31, wid = tid >> 5;

    int p = (tid < b && tid < SCAN_GRID) ? g_poff[tid] : 0;
#pragma unroll
    for (int o = 16; o > 0; o >>= 1) p += __shfl_down_sync(0xffffffffu, p, o);
    if (lane == 0) ws[wid] = p;
    __syncthreads();
    if (wid == 0) {
        int s = (lane < 8) ? ws[lane] : 0;
#pragma unroll
        for (int o = 4; o > 0; o >>= 1) s += __shfl_down_sync(0xffffffffu, s, o);
        if (lane == 0) s_off = s;
    }
    __syncthreads();

    int i = b * SCAN_B + tid;
    int v = (i < NN) ? g_inc[i] : 0;
    int x = v;
#pragma unroll
    for (int o = 1; o < 32; o <<= 1) {
        int y = __shfl_up_sync(0xffffffffu, x, o);
        if (lane >= o) x += y;
    }
    __syncthreads();
    if (lane == 31) ws[wid] = x;
    __syncthreads();
    if (wid == 0 && lane < 8) {
        int s = ws[lane];
        int xs = s;
#pragma unroll
        for (int o = 1; o < 8; o <<= 1) {
            int y = __shfl_up_sync(0xffu, xs, o);
            if (lane >= o) xs += y;
        }
        ws[lane] = xs - s;
    }
    __syncthreads();
    if (i < NN) {
        int excl = s_off + ws[wid] + x - v;
        g_rowptr[i] = excl;
        g_cursor[i] = excl;
    }
    if (b == 0 && tid == 0) g_rowptr[NN] = NE;
}

// 2 edges per thread
__global__ void k_csr_fill(const int* __restrict__ src, const int* __restrict__ dst) {
    int e = (blockIdx.x * blockDim.x + threadIdx.x) * 2;
    if (e + 1 < NE) {
        int2 s = *(const int2*)(src + e);
        int2 d = *(const int2*)(dst + e);
        int p0 = atomicAdd(&g_cursor[d.x], 1);
        g_csrc[p0] = s.x;
        int p1 = atomicAdd(&g_cursor[d.y], 1);
        g_csrc[p1] = s.y;
    } else if (e < NE) {
        int pos = atomicAdd(&g_cursor[dst[e]], 1);
        g_csrc[pos] = src[e];
    }
}

// ---------------- fp16 gather SpMM + fused epilogues ----------------
__device__ __forceinline__ void acc8_f16(float* a, uint4 v, float s) {
    __half2 p0 = *(__half2*)&v.x;
    __half2 p1 = *(__half2*)&v.y;
    __half2 p2 = *(__half2*)&v.z;
    __half2 p3 = *(__half2*)&v.w;
    float2 f0 = __half22float2(p0);
    float2 f1 = __half22float2(p1);
    float2 f2 = __half22float2(p2);
    float2 f3 = __half22float2(p3);
    a[0] = fmaf(f0.x, s, a[0]); a[1] = fmaf(f0.y, s, a[1]);
    a[2] = fmaf(f1.x, s, a[2]); a[3] = fmaf(f1.y, s, a[3]);
    a[4] = fmaf(f2.x, s, a[4]); a[5] = fmaf(f2.y, s, a[5]);
    a[6] = fmaf(f3.x, s, a[6]); a[7] = fmaf(f3.y, s, a[7]);
}

// h = relu(in_norm * sum outnorm[src]*t[src] + b1) for nodes [n0, n1)
__global__ void k_gather_h(const __half* __restrict__ t, const float* __restrict__ b1,
                           float* __restrict__ h, __half* __restrict__ hh,
                           int n0, int n1) {
    int node = n0 + ((blockIdx.x * blockDim.x + threadIdx.x) >> 5);
    int lane = threadIdx.x & 31;
    if (node >= n1) return;
    int beg = g_rowptr[node], end = g_rowptr[node + 1];
    float a[8];
#pragma unroll
    for (int i = 0; i < 8; i++) a[i] = 0.f;
    int j = beg;
    for (; j + 3 < end; j += 4) {
        int s0 = g_csrc[j],     s1 = g_csrc[j + 1];
        int s2 = g_csrc[j + 2], s3 = g_csrc[j + 3];
        float on0 = g_outnorm[s0], on1 = g_outnorm[s1];
        float on2 = g_outnorm[s2], on3 = g_outnorm[s3];
        uint4 v0 = ((const uint4*)(t + (size_t)s0 * DHID))[lane];
        uint4 v1 = ((const uint4*)(t + (size_t)s1 * DHID))[lane];
        uint4 v2 = ((const uint4*)(t + (size_t)s2 * DHID))[lane];
        uint4 v3 = ((const uint4*)(t + (size_t)s3 * DHID))[lane];
        acc8_f16(a, v0, on0);
        acc8_f16(a, v1, on1);
        acc8_f16(a, v2, on2);
        acc8_f16(a, v3, on3);
    }
    for (; j < end; j++) {
        int s0 = g_csrc[j];
        float on0 = g_outnorm[s0];
        uint4 v = ((const uint4*)(t + (size_t)s0 * DHID))[lane];
        acc8_f16(a, v, on0);
    }
    float s = g_innorm[node];
    const float* bp = b1 + lane * 8;
    float4 bb0 = *(const float4*)bp;
    float4 bb1 = *(const float4*)(bp + 4);
    float4 o0, o1;
    o0.x = fmaxf(fmaf(a[0], s, bb0.x), 0.f); o0.y = fmaxf(fmaf(a[1], s, bb0.y), 0.f);
    o0.z = fmaxf(fmaf(a[2], s, bb0.z), 0.f); o0.w = fmaxf(fmaf(a[3], s, bb0.w), 0.f);
    o1.x = fmaxf(fmaf(a[4], s, bb1.x), 0.f); o1.y = fmaxf(fmaf(a[5], s, bb1.y), 0.f);
    o1.z = fmaxf(fmaf(a[6], s, bb1.z), 0.f); o1.w = fmaxf(fmaf(a[7], s, bb1.w), 0.f);
    float* hp = h + (size_t)node * DHID + lane * 8;
    *(float4*)hp = o0;
    *(float4*)(hp + 4) = o1;
    __half2 q0 = __float22half2_rn(make_float2(o0.x, o0.y));
    __half2 q1 = __float22half2_rn(make_float2(o0.z, o0.w));
    __half2 q2 = __float22half2_rn(make_float2(o1.x, o1.y));
    __half2 q3 = __float22half2_rn(make_float2(o1.z, o1.w));
    uint4 q;
    q.x = *(uint32_t*)&q0; q.y = *(uint32_t*)&q1;
    q.z = *(uint32_t*)&q2; q.w = *(uint32_t*)&q3;
    ((uint4*)(hh + (size_t)node * DHID))[lane] = q;
}

// z = relu(mean*in + b2) + noise * exp(logstd*in + b3)
__global__ void k_gather_z(const __half* __restrict__ t,
                           const float* __restrict__ b2, const float* __restrict__ b3,
                           const float* __restrict__ noise, float* __restrict__ z) {
    int node = (blockIdx.x * blockDim.x + threadIdx.x) >> 5;
    int lane = threadIdx.x & 31;
    if (node >= NN) return;
    int beg = g_rowptr[node], end = g_rowptr[node + 1];
    float a[8];
#pragma unroll
    for (int i = 0; i < 8; i++) a[i] = 0.f;
    int j = beg;
    for (; j + 3 < end; j += 4) {
        int s0 = g_csrc[j],     s1 = g_csrc[j + 1];
        int s2 = g_csrc[j + 2], s3 = g_csrc[j + 3];
        uint4 v0 = ((const uint4*)(t + (size_t)s0 * DHID))[lane];
        uint4 v1 = ((const uint4*)(t + (size_t)s1 * DHID))[lane];
        uint4 v2 = ((const uint4*)(t + (size_t)s2 * DHID))[lane];
        uint4 v3 = ((const uint4*)(t + (size_t)s3 * DHID))[lane];
        acc8_f16(a, v0, 1.f);
        acc8_f16(a, v1, 1.f);
        acc8_f16(a, v2, 1.f);
        acc8_f16(a, v3, 1.f);
    }
    for (; j < end; j++) {
        uint4 v = ((const uint4*)(t + (size_t)g_csrc[j] * DHID))[lane];
        acc8_f16(a, v, 1.f);
    }
    float l[8];
#pragma unroll
    for (int i = 0; i < 8; i++) l[i] = __shfl_down_sync(0xffffffffu, a[i], 16);
    if (lane < 16) {
        float s = g_innorm[node];
        const float* bmp = b2 + lane * 8;
        const float* blp = b3 + lane * 8;
        const float* nvp = noise + (size_t)node * DOUT + lane * 8;
        float4 bm0 = *(const float4*)bmp,        bm1 = *(const float4*)(bmp + 4);
        float4 bl0 = *(const float4*)blp,        bl1 = *(const float4*)(blp + 4);
        float4 n0  = *(const float4*)nvp,        n1  = *(const float4*)(nvp + 4);
        float4 r0, r1;
        r0.x = fmaxf(fmaf(a[0], s, bm0.x), 0.f) + n0.x * expf(fmaf(l[0], s, bl0.x));
        r0.y = fmaxf(fmaf(a[1], s, bm0.y), 0.f) + n0.y * expf(fmaf(l[1], s, bl0.y));
        r0.z = fmaxf(fmaf(a[2], s, bm0.z), 0.f) + n0.z * expf(fmaf(l[2], s, bl0.z));
        r0.w = fmaxf(fmaf(a[3], s, bm0.w), 0.f) + n0.w * expf(fmaf(l[3], s, bl0.w));
        r1.x = fmaxf(fmaf(a[4], s, bm1.x), 0.f) + n1.x * expf(fmaf(l[4], s, bl1.x));
        r1.y = fmaxf(fmaf(a[5], s, bm1.y), 0.f) + n1.y * expf(fmaf(l[5], s, bl1.y));
        r1.z = fmaxf(fmaf(a[6], s, bm1.z), 0.f) + n1.z * expf(fmaf(l[6], s, bl1.z));
        r1.w = fmaxf(fmaf(a[7], s, bm1.w), 0.f) + n1.w * expf(fmaf(l[7], s, bl1.w));
        float* zp = z + (size_t)node * DOUT + lane * 8;
        *(float4*)zp = r0;
        *(float4*)(zp + 4) = r1;
    }
}

// ---------------- fp16 mma / cp.async helpers ----------------
__device__ __forceinline__ void mma_f16(float* c, const uint32_t* a, const uint32_t* b) {
    asm volatile(
        "mma.sync.aligned.m16n8k16.row.col.f32.f16.f16.f32 "
        "{%0,%1,%2,%3}, {%4,%5,%6,%7}, {%8,%9}, {%0,%1,%2,%3};"
        : "+f"(c[0]), "+f"(c[1]), "+f"(c[2]), "+f"(c[3])
        : "r"(a[0]), "r"(a[1]), "r"(a[2]), "r"(a[3]), "r"(b[0]), "r"(b[1]));
}

__device__ __forceinline__ void cp16(uint32_t dst, const void* src) {
    asm volatile("cp.async.cg.shared.global [%0], [%1], 16;" :: "r"(dst), "l"(src));
}
__device__ __forceinline__ void cp_commit() { asm volatile("cp.async.commit_group;"); }
template<int N>
__device__ __forceinline__ void cp_wait() { asm volatile("cp.async.wait_group %0;" :: "n"(N)); }

// ---------------- fp16 tensor-core GEMM (3-stage cp.async pipeline) ----------------
template<int OUTHALF>
__global__ void __launch_bounds__(256, 2)
k_gemm_f16(const __half* __restrict__ A, const float* __restrict__ rowscale,
           const __half* __restrict__ B, void* __restrict__ Cv, int M)
{
    constexpr int K = 256, NCOLS = 256;
    constexpr int BM = 128, BN = 128, BK = 32;
    constexpr int ALD = 40;
    constexpr int ST = 3;
    __shared__ __align__(16) __half As[ST][BM * ALD];
    __shared__ __align__(16) __half Bs[ST][BN * ALD];

    const int tid  = threadIdx.x;
    const int lane = tid & 31;
    const int warp = tid >> 5;
    const int row0 = blockIdx.y * BM;
    const int col0 = blockIdx.x * BN;
    const int warpM = (warp >> 2) * 64;
    const int warpN = (warp & 3) * 32;

    float acc[4][4][4];
#pragma unroll
    for (int i = 0; i < 4; i++)
#pragma unroll
        for (int j = 0; j < 4; j++)
#pragma unroll
            for (int r = 0; r < 4; r++) acc[i][j][r] = 0.f;

    auto stage = [&](int k0, int buf) {
#pragma unroll
        for (int i = 0; i < 2; i++) {
            int c = tid * 2 + i;
            int r = c >> 2;
            int off = (c & 3) * 8;
            int gr = row0 + r;
            if (gr >= M) gr = M - 1;
            cp16((uint32_t)__cvta_generic_to_shared(&As[buf][r * ALD + off]),
                 A + (size_t)gr * K + k0 + off);
            cp16((uint32_t)__cvta_generic_to_shared(&Bs[buf][r * ALD + off]),
                 B + (size_t)(col0 + r) * K + k0 + off);
        }
    };

    const int NT = K / BK;
    stage(0, 0);
    cp_commit();
    stage(BK, 1);
    cp_commit();

    for (int t = 0; t < NT; t++) {
        int buf = t % ST;
        if (t < NT - 1) cp_wait<1>(); else cp_wait<0>();
        __syncthreads();
        if (t + 2 < NT) {
            stage((t + 2) * BK, (t + 2) % ST);
            cp_commit();
        }

#pragma unroll
        for (int ks = 0; ks < 2; ks++) {
            const int kb = ks * 16 + (lane & 3) * 2;
            uint32_t a[4][4], b[4][2];
#pragma unroll
            for (int mi = 0; mi < 4; mi++) {
                const __half* ap = &As[buf][(warpM + mi * 16 + (lane >> 2)) * ALD + kb];
                a[mi][0] = *(const uint32_t*)ap;
                a[mi][1] = *(const uint32_t*)(ap + 8 * ALD);
                a[mi][2] = *(const uint32_t*)(ap + 8);
                a[mi][3] = *(const uint32_t*)(ap + 8 * ALD + 8);
            }
#pragma unroll
            for (int ni = 0; ni < 4; ni++) {
                const __half* bp = &Bs[buf][(warpN + ni * 8 + (lane >> 2)) * ALD + kb];
                b[ni][0] = *(const uint32_t*)bp;
                b[ni][1] = *(const uint32_t*)(bp + 8);
            }
#pragma unroll
            for (int mi = 0; mi < 4; mi++)
#pragma unroll
                for (int ni = 0; ni < 4; ni++)
                    mma_f16(acc[mi][ni], a[mi], b[ni]);
        }
    }

#pragma unroll
    for (int mi = 0; mi < 4; mi++) {
        int gr0 = row0 + warpM + mi * 16 + (lane >> 2);
        float s0 = 1.f, s1 = 1.f;
        if (rowscale) {
            if (gr0 < M)     s0 = rowscale[gr0];
            if (gr0 + 8 < M) s1 = rowscale[gr0 + 8];
        }
#pragma unroll
        for (int ni = 0; ni < 4; ni++) {
            int col = col0 + warpN + ni * 8 + (lane & 3) * 2;
            if constexpr (OUTHALF) {
                __half* Ch = (__half*)Cv;
                if (gr0 < M)
                    *(__half2*)(Ch + (size_t)gr0 * NCOLS + col) =
                        __float22half2_rn(make_float2(acc[mi][ni][0] * s0, acc[mi][ni][1] * s0));
                if (gr0 + 8 < M)
                    *(__half2*)(Ch + (size_t)(gr0 + 8) * NCOLS + col) =
                        __float22half2_rn(make_float2(acc[mi][ni][2] * s1, acc[mi][ni][3] * s1));
            } else {
                float* C = (float*)Cv;
                if (gr0 < M)
                    *(float2*)(C + (size_t)gr0 * NCOLS + col) =
                        make_float2(acc[mi][ni][0] * s0, acc[mi][ni][1] * s0);
                if (gr0 + 8 < M)
                    *(float2*)(C + (size_t)(gr0 + 8) * NCOLS + col) =
                        make_float2(acc[mi][ni][2] * s1, acc[mi][ni][3] * s1);
            }
        }
    }
}

// ---------------- stream/event singletons (host resources, created once) ----------
namespace {
struct HxRes {
    cudaStream_t s_pre = nullptr, s_g3 = nullptr, s_g2 = nullptr;
    cudaEvent_t  e_fork = nullptr, e_csr = nullptr,
                 e_g1 = nullptr, e_g3 = nullptr, e_gh1 = nullptr, e_g2 = nullptr,
                 e_zero = nullptr;
    HxRes() {
        cudaStreamCreateWithFlags(&s_pre, cudaStreamNonBlocking);
        cudaStreamCreateWithFlags(&s_g3,  cudaStreamNonBlocking);
        cudaStreamCreateWithFlags(&s_g2,  cudaStreamNonBlocking);
        cudaEventCreateWithFlags(&e_fork, cudaEventDisableTiming);
        cudaEventCreateWithFlags(&e_csr,  cudaEventDisableTiming);
        cudaEventCreateWithFlags(&e_g1,   cudaEventDisableTiming);
        cudaEventCreateWithFlags(&e_g3,   cudaEventDisableTiming);
        cudaEventCreateWithFlags(&e_gh1,  cudaEventDisableTiming);
        cudaEventCreateWithFlags(&e_g2,   cudaEventDisableTiming);
        cudaEventCreateWithFlags(&e_zero, cudaEventDisableTiming);
    }
};
HxRes g_res;
}

// ---------------- launch ----------------
extern "C" void kernel_launch(void* const* d_in, const int* in_sizes, int n_in,
                              void* d_out, int out_size)
{
    const float* features = (const float*)d_in[0];
    const float* noise    = (const float*)d_in[1];
    const float* W1       = (const float*)d_in[2];
    const float* b1       = (const float*)d_in[3];
    const float* W2       = (const float*)d_in[4];
    const float* b2       = (const float*)d_in[5];
    const float* W3       = (const float*)d_in[6];
    const float* b3       = (const float*)d_in[7];
    const float* fcW      = (const float*)d_in[8];
    const int*   src      = (const int*)d_in[9];
    const int*   dst      = (const int*)d_in[10];

    float* out     = (float*)d_out;
    float* z_out   = out;                                 // [NN, 128]
    float* h_out   = out + (size_t)NN * DOUT;             // [NN, 256]
    float* seq_out = h_out + (size_t)NN * DHID;           // [NN, 256]

    __half *pth, *phh, *pfh, *pw1, *pw23, *pfcw;
    float  *pon;
    cudaGetSymbolAddress((void**)&pth,  g_th);
    cudaGetSymbolAddress((void**)&phh,  g_hh);
    cudaGetSymbolAddress((void**)&pfh,  g_fh);
    cudaGetSymbolAddress((void**)&pw1,  g_w1h);
    cudaGetSymbolAddress((void**)&pw23, g_w23h);
    cudaGetSymbolAddress((void**)&pfcw, g_fcwh);
    cudaGetSymbolAddress((void**)&pon,  g_outnorm);

    const int T = 256;
    dim3 ggrid(2, (NN + 127) / 128);
    dim3 ggrid_lo(2, MID / 128);
    dim3 ggrid_hi(2, (NN - MID + 127) / 128);

    // ---- fork: CSR prologue on side stream (independent of conversions) ----
    cudaEventRecord(g_res.e_fork, 0);
    cudaStreamWaitEvent(g_res.s_pre, g_res.e_fork, 0);
    k_degree<<<(NE / 2 + T - 1) / T, T, 0, g_res.s_pre>>>(src, dst);
    k_scan_p1n<<<SCAN_GRID, SCAN_B, 0, g_res.s_pre>>>();
    k_scan_p3f<<<SCAN_GRID, SCAN_B, 0, g_res.s_pre>>>();
    k_csr_fill<<<(NE / 2 + T - 1) / T, T, 0, g_res.s_pre>>>(src, dst);
    cudaEventRecord(g_res.e_csr, g_res.s_pre);
    // tail: re-zero counters in the shadow of main-stream work
    k_zero_counts<<<(NN + T - 1) / T, T, 0, g_res.s_pre>>>();
    cudaEventRecord(g_res.e_zero, g_res.s_pre);

    // ---- main: all conversions in one kernel, then gemm1 (no cross-stream wait) ----
    k_conv_all<<<(CONV_TOTAL + T - 1) / T, T>>>(features, W1, W2, W3, fcW);
    k_gemm_f16<1><<<ggrid, T>>>(pfh, nullptr, pw1, pth, NN);
    cudaEventRecord(g_res.e_g1, 0);

    // ---- side: gemm3 (seq_fts) after gemm1, overlapping the rest ----
    cudaStreamWaitEvent(g_res.s_g3, g_res.e_g1, 0);
    k_gemm_f16<0><<<ggrid, T, 0, g_res.s_g3>>>(pfh, nullptr, pfcw, seq_out, NN);
    cudaEventRecord(g_res.e_g3, g_res.s_g3);

    // ---- main: join CSR; gather_h split into halves ----
    cudaStreamWaitEvent(0, g_res.e_csr, 0);
    k_gather_h<<<(MID * 32 + T - 1) / T, T>>>(pth, b1, h_out, phh, 0, MID);
    cudaEventRecord(g_res.e_gh1, 0);
    k_gather_h<<<((NN - MID) * 32 + T - 1) / T, T>>>(pth, b1, h_out, phh, MID, NN);

    // ---- side: gemm2 lower half overlaps gather_h upper half ----
    cudaStreamWaitEvent(g_res.s_g2, g_res.e_gh1, 0);
    k_gemm_f16<1><<<ggrid_lo, T, 0, g_res.s_g2>>>(phh, pon, pw23, pth, MID);
    cudaEventRecord(g_res.e_g2, g_res.s_g2);

    // ---- main: gemm2 upper half, join lower, gather_z ----
    k_gemm_f16<1><<<ggrid_hi, T>>>(phh + (size_t)MID * DHID, pon + MID, pw23,
                                   pth + (size_t)MID * DHID, NN - MID);
    cudaStreamWaitEvent(0, g_res.e_g2, 0);
    k_gather_z<<<(NN * 32 + T - 1) / T, T>>>(pth, b2, b3, noise, z_out);

    // ---- final joins: seq_fts + counter re-zero must complete before graph end ----
    cudaStreamWaitEvent(0, g_res.e_g3, 0);
    cudaStreamWaitEvent(0, g_res.e_zero, 0);
}

// round 16
// speedup vs baseline: 1.0032x; 1.0032x over previous
#include <cuda_runtime.h>
#include <cuda_fp16.h>
#include <cstdint>
#include <cstddef>

#define NN   50000
#define NE   800000
#define DIN  256
#define DHID 256
#define DOUT 128
#define MID  25088    // gather_h/gemm2 split point (multiple of 128)

#define SCAN_B 256
#define SCAN_GRID ((NN + SCAN_B - 1) / SCAN_B)   // 196

// ---------------- scratch (device globals; no allocation allowed) ----------------
// g_outc/g_inc rely on zero-initialization at module load; every call re-zeroes
// them at its tail (shadowed), so each invocation starts from zeros.
__device__ float g_outnorm[NN];
__device__ float g_innorm[NN];
__device__ int   g_outc[NN];
__device__ int   g_inc[NN];
__device__ int   g_rowptr[NN + 1];
__device__ int   g_cursor[NN];
__device__ int   g_poff[SCAN_B];                 // per-block inc sums
__device__ int   g_csrc[NE];                     // src node per CSR slot (by dst)
__device__ __half g_th[(size_t)NN * DHID];       // pre-agg features t (fp16)
__device__ __half g_hh[(size_t)NN * DHID];       // fp16 copy of h (gemm2 input)
__device__ __half g_fh[(size_t)NN * DIN];        // fp16 features
__device__ __half g_w1h[DIN * DHID];             // W1^T  [n][k] fp16
__device__ __half g_w23h[DHID * DHID];           // [W2|W3]^T [n][k] fp16
__device__ __half g_fcwh[DHID * DIN];            // fcW (already [n][k]) fp16

// ---------------- unified conversion kernel ----------------
#define CONV_FEAT_T (NN * (DIN / 4))             // 3,200,000
#define CONV_TOTAL  (CONV_FEAT_T + 3 * 65536)

__global__ void k_conv_all(const float* __restrict__ f,
                           const float* __restrict__ W1, const float* __restrict__ W2,
                           const float* __restrict__ W3, const float* __restrict__ fcW) {
    int t = blockIdx.x * blockDim.x + threadIdx.x;
    if (t < CONV_FEAT_T) {
        float4 v = ((const float4*)f)[t];
        __half2 h0 = __float22half2_rn(make_float2(v.x, v.y));
        __half2 h1 = __float22half2_rn(make_float2(v.z, v.w));
        uint2 o;
        o.x = *(uint32_t*)&h0;
        o.y = *(uint32_t*)&h1;
        ((uint2*)g_fh)[t] = o;
        return;
    }
    int w = t - CONV_FEAT_T;
    if (w < 65536) {                              // W1 -> g_w1h transposed
        int n = w >> 8, k = w & 255;
        g_w1h[w] = __float2half(W1[k * 256 + n]);
    } else if (w < 131072) {                      // fcW -> g_fcwh direct
        int i = w - 65536;
        g_fcwh[i] = __float2half(fcW[i]);
    } else if (w < 196608) {                      // W2|W3 -> g_w23h transposed
        int i = w - 131072;
        int hs = i >> 15;
        int j = i & 32767;
        int n = j >> 8, k = j & 255;
        const float* S = hs ? W3 : W2;
        g_w23h[(size_t)(hs * 128 + n) * 256 + k] = __float2half(S[k * 128 + n]);
    }
}

// ---------------- degree / norm / CSR kernels ----------------
// 4 edges per thread: all loads first, then 8 independent atomics (MLP=8)
__global__ void k_degree(const int* __restrict__ src, const int* __restrict__ dst) {
    int e = (blockIdx.x * blockDim.x + threadIdx.x) * 4;
    if (e + 3 < NE) {
        int4 s = *(const int4*)(src + e);
        int4 d = *(const int4*)(dst + e);
        atomicAdd(&g_outc[s.x], 1);
        atomicAdd(&g_outc[s.y], 1);
        atomicAdd(&g_outc[s.z], 1);
        atomicAdd(&g_outc[s.w], 1);
        atomicAdd(&g_inc[d.x], 1);
        atomicAdd(&g_inc[d.y], 1);
        atomicAdd(&g_inc[d.z], 1);
        atomicAdd(&g_inc[d.w], 1);
    } else {
        for (; e < NE; e++) {
            atomicAdd(&g_outc[src[e]], 1);
            atomicAdd(&g_inc[dst[e]], 1);
        }
    }
}

// tail zeroing (runs shadowed at graph end; restores zero-state for next replay)
__global__ void k_zero_counts() {
    int i = blockIdx.x * blockDim.x + threadIdx.x;
    if (i < NN) { g_outc[i] = 0; g_inc[i] = 0; }
}

// phase 1 (fused with norms): per-block inc sums + out/in norms
__global__ void k_scan_p1n() {
    __shared__ int ws[8];
    int i = blockIdx.x * SCAN_B + threadIdx.x;
    int lane = threadIdx.x & 31, wid = threadIdx.x >> 5;
    int v = 0;
    if (i < NN) {
        int oc = g_outc[i];
        v = g_inc[i];
        g_outnorm[i] = rsqrtf(fmaxf((float)oc, 1.f));
        g_innorm[i]  = rsqrtf(fmaxf((float)v, 1.f));
    }
    int x = v;
#pragma unroll
    for (int o = 16; o > 0; o >>= 1) x += __shfl_down_sync(0xffffffffu, x, o);
    if (lane == 0) ws[wid] = x;
    __syncthreads();
    if (wid == 0) {
        int s = (lane < 8) ? ws[lane] : 0;
#pragma unroll
        for (int o = 4; o > 0; o >>= 1) s += __shfl_down_sync(0xffffffffu, s, o);
        if (lane == 0) g_poff[blockIdx.x] = s;
    }
}

// phase 2+3 fused: each block reduces g_poff[0..b) itself, then local scan.
__global__ void k_scan_p3f() {
    __shared__ int ws[8];
    __shared__ int s_off;
    const int b = blockIdx.x;
    int tid = threadIdx.x, lane = tid & 31, wid = tid >> 5;

    int p = (tid < b && tid < SCAN_GRID) ? g_poff[tid] : 0;
#pragma unroll
    for (int o = 16; o > 0; o >>= 1) p += __shfl_down_sync(0xffffffffu, p, o);
    if (lane == 0) ws[wid] = p;
    __syncthreads();
    if (wid == 0) {
        int s = (lane < 8) ? ws[lane] : 0;
#pragma unroll
        for (int o = 4; o > 0; o >>= 1) s += __shfl_down_sync(0xffffffffu, s, o);
        if (lane == 0) s_off = s;
    }
    __syncthreads();

    int i = b * SCAN_B + tid;
    int v = (i < NN) ? g_inc[i] : 0;
    int x = v;
#pragma unroll
    for (int o = 1; o < 32; o <<= 1) {
        int y = __shfl_up_sync(0xffffffffu, x, o);
        if (lane >= o) x += y;
    }
    __syncthreads();
    if (lane == 31) ws[wid] = x;
    __syncthreads();
    if (wid == 0 && lane < 8) {
        int s = ws[lane];
        int xs = s;
#pragma unroll
        for (int o = 1; o < 8; o <<= 1) {
            int y = __shfl_up_sync(0xffu, xs, o);
            if (lane >= o) xs += y;
        }
        ws[lane] = xs - s;
    }
    __syncthreads();
    if (i < NN) {
        int excl = s_off + ws[wid] + x - v;
        g_rowptr[i] = excl;
        g_cursor[i] = excl;
    }
    if (b == 0 && tid == 0) g_rowptr[NN] = NE;
}

// 4 edges per thread: loads first, 4 independent atomic+store chains in flight
__global__ void k_csr_fill(const int* __restrict__ src, const int* __restrict__ dst) {
    int e = (blockIdx.x * blockDim.x + threadIdx.x) * 4;
    if (e + 3 < NE) {
        int4 s = *(const int4*)(src + e);
        int4 d = *(const int4*)(dst + e);
        int p0 = atomicAdd(&g_cursor[d.x], 1);
        int p1 = atomicAdd(&g_cursor[d.y], 1);
        int p2 = atomicAdd(&g_cursor[d.z], 1);
        int p3 = atomicAdd(&g_cursor[d.w], 1);
        g_csrc[p0] = s.x;
        g_csrc[p1] = s.y;
        g_csrc[p2] = s.z;
        g_csrc[p3] = s.w;
    } else {
        for (; e < NE; e++) {
            int pos = atomicAdd(&g_cursor[dst[e]], 1);
            g_csrc[pos] = src[e];
        }
    }
}

// ---------------- fp16 gather SpMM + fused epilogues ----------------
__device__ __forceinline__ void acc8_f16(float* a, uint4 v, float s) {
    __half2 p0 = *(__half2*)&v.x;
    __half2 p1 = *(__half2*)&v.y;
    __half2 p2 = *(__half2*)&v.z;
    __half2 p3 = *(__half2*)&v.w;
    float2 f0 = __half22float2(p0);
    float2 f1 = __half22float2(p1);
    float2 f2 = __half22float2(p2);
    float2 f3 = __half22float2(p3);
    a[0] = fmaf(f0.x, s, a[0]); a[1] = fmaf(f0.y, s, a[1]);
    a[2] = fmaf(f1.x, s, a[2]); a[3] = fmaf(f1.y, s, a[3]);
    a[4] = fmaf(f2.x, s, a[4]); a[5] = fmaf(f2.y, s, a[5]);
    a[6] = fmaf(f3.x, s, a[6]); a[7] = fmaf(f3.y, s, a[7]);
}

// h = relu(in_norm * sum outnorm[src]*t[src] + b1) for nodes [n0, n1)
__global__ void k_gather_h(const __half* __restrict__ t, const float* __restrict__ b1,
                           float* __restrict__ h, __half* __restrict__ hh,
                           int n0, int n1) {
    int node = n0 + ((blockIdx.x * blockDim.x + threadIdx.x) >> 5);
    int lane = threadIdx.x & 31;
    if (node >= n1) return;
    int beg = g_rowptr[node], end = g_rowptr[node + 1];
    float a[8];
#pragma unroll
    for (int i = 0; i < 8; i++) a[i] = 0.f;
    int j = beg;
    for (; j + 3 < end; j += 4) {
        int s0 = g_csrc[j],     s1 = g_csrc[j + 1];
        int s2 = g_csrc[j + 2], s3 = g_csrc[j + 3];
        float on0 = g_outnorm[s0], on1 = g_outnorm[s1];
        float on2 = g_outnorm[s2], on3 = g_outnorm[s3];
        uint4 v0 = ((const uint4*)(t + (size_t)s0 * DHID))[lane];
        uint4 v1 = ((const uint4*)(t + (size_t)s1 * DHID))[lane];
        uint4 v2 = ((const uint4*)(t + (size_t)s2 * DHID))[lane];
        uint4 v3 = ((const uint4*)(t + (size_t)s3 * DHID))[lane];
        acc8_f16(a, v0, on0);
        acc8_f16(a, v1, on1);
        acc8_f16(a, v2, on2);
        acc8_f16(a, v3, on3);
    }
    for (; j < end; j++) {
        int s0 = g_csrc[j];
        float on0 = g_outnorm[s0];
        uint4 v = ((const uint4*)(t + (size_t)s0 * DHID))[lane];
        acc8_f16(a, v, on0);
    }
    float s = g_innorm[node];
    const float* bp = b1 + lane * 8;
    float4 bb0 = *(const float4*)bp;
    float4 bb1 = *(const float4*)(bp + 4);
    float4 o0, o1;
    o0.x = fmaxf(fmaf(a[0], s, bb0.x), 0.f); o0.y = fmaxf(fmaf(a[1], s, bb0.y), 0.f);
    o0.z = fmaxf(fmaf(a[2], s, bb0.z), 0.f); o0.w = fmaxf(fmaf(a[3], s, bb0.w), 0.f);
    o1.x = fmaxf(fmaf(a[4], s, bb1.x), 0.f); o1.y = fmaxf(fmaf(a[5], s, bb1.y), 0.f);
    o1.z = fmaxf(fmaf(a[6], s, bb1.z), 0.f); o1.w = fmaxf(fmaf(a[7], s, bb1.w), 0.f);
    float* hp = h + (size_t)node * DHID + lane * 8;
    *(float4*)hp = o0;
    *(float4*)(hp + 4) = o1;
    __half2 q0 = __float22half2_rn(make_float2(o0.x, o0.y));
    __half2 q1 = __float22half2_rn(make_float2(o0.z, o0.w));
    __half2 q2 = __float22half2_rn(make_float2(o1.x, o1.y));
    __half2 q3 = __float22half2_rn(make_float2(o1.z, o1.w));
    uint4 q;
    q.x = *(uint32_t*)&q0; q.y = *(uint32_t*)&q1;
    q.z = *(uint32_t*)&q2; q.w = *(uint32_t*)&q3;
    ((uint4*)(hh + (size_t)node * DHID))[lane] = q;
}

// z = relu(mean*in + b2) + noise * exp(logstd*in + b3)
__global__ void k_gather_z(const __half* __restrict__ t,
                           const float* __restrict__ b2, const float* __restrict__ b3,
                           const float* __restrict__ noise, float* __restrict__ z) {
    int node = (blockIdx.x * blockDim.x + threadIdx.x) >> 5;
    int lane = threadIdx.x & 31;
    if (node >= NN) return;
    int beg = g_rowptr[node], end = g_rowptr[node + 1];
    float a[8];
#pragma unroll
    for (int i = 0; i < 8; i++) a[i] = 0.f;
    int j = beg;
    for (; j + 3 < end; j += 4) {
        int s0 = g_csrc[j],     s1 = g_csrc[j + 1];
        int s2 = g_csrc[j + 2], s3 = g_csrc[j + 3];
        uint4 v0 = ((const uint4*)(t + (size_t)s0 * DHID))[lane];
        uint4 v1 = ((const uint4*)(t + (size_t)s1 * DHID))[lane];
        uint4 v2 = ((const uint4*)(t + (size_t)s2 * DHID))[lane];
        uint4 v3 = ((const uint4*)(t + (size_t)s3 * DHID))[lane];
        acc8_f16(a, v0, 1.f);
        acc8_f16(a, v1, 1.f);
        acc8_f16(a, v2, 1.f);
        acc8_f16(a, v3, 1.f);
    }
    for (; j < end; j++) {
        uint4 v = ((const uint4*)(t + (size_t)g_csrc[j] * DHID))[lane];
        acc8_f16(a, v, 1.f);
    }
    float l[8];
#pragma unroll
    for (int i = 0; i < 8; i++) l[i] = __shfl_down_sync(0xffffffffu, a[i], 16);
    if (lane < 16) {
        float s = g_innorm[node];
        const float* bmp = b2 + lane * 8;
        const float* blp = b3 + lane * 8;
        const float* nvp = noise + (size_t)node * DOUT + lane * 8;
        float4 bm0 = *(const float4*)bmp,        bm1 = *(const float4*)(bmp + 4);
        float4 bl0 = *(const float4*)blp,        bl1 = *(const float4*)(blp + 4);
        float4 n0  = *(const float4*)nvp,        n1  = *(const float4*)(nvp + 4);
        float4 r0, r1;
        r0.x = fmaxf(fmaf(a[0], s, bm0.x), 0.f) + n0.x * expf(fmaf(l[0], s, bl0.x));
        r0.y = fmaxf(fmaf(a[1], s, bm0.y), 0.f) + n0.y * expf(fmaf(l[1], s, bl0.y));
        r0.z = fmaxf(fmaf(a[2], s, bm0.z), 0.f) + n0.z * expf(fmaf(l[2], s, bl0.z));
        r0.w = fmaxf(fmaf(a[3], s, bm0.w), 0.f) + n0.w * expf(fmaf(l[3], s, bl0.w));
        r1.x = fmaxf(fmaf(a[4], s, bm1.x), 0.f) + n1.x * expf(fmaf(l[4], s, bl1.x));
        r1.y = fmaxf(fmaf(a[5], s, bm1.y), 0.f) + n1.y * expf(fmaf(l[5], s, bl1.y));
        r1.z = fmaxf(fmaf(a[6], s, bm1.z), 0.f) + n1.z * expf(fmaf(l[6], s, bl1.z));
        r1.w = fmaxf(fmaf(a[7], s, bm1.w), 0.f) + n1.w * expf(fmaf(l[7], s, bl1.w));
        float* zp = z + (size_t)node * DOUT + lane * 8;
        *(float4*)zp = r0;
        *(float4*)(zp + 4) = r1;
    }
}

// ---------------- fp16 mma / cp.async helpers ----------------
__device__ __forceinline__ void mma_f16(float* c, const uint32_t* a, const uint32_t* b) {
    asm volatile(
        "mma.sync.aligned.m16n8k16.row.col.f32.f16.f16.f32 "
        "{%0,%1,%2,%3}, {%4,%5,%6,%7}, {%8,%9}, {%0,%1,%2,%3};"
        : "+f"(c[0]), "+f"(c[1]), "+f"(c[2]), "+f"(c[3])
        : "r"(a[0]), "r"(a[1]), "r"(a[2]), "r"(a[3]), "r"(b[0]), "r"(b[1]));
}

__device__ __forceinline__ void cp16(uint32_t dst, const void* src) {
    asm volatile("cp.async.cg.shared.global [%0], [%1], 16;" :: "r"(dst), "l"(src));
}
__device__ __forceinline__ void cp_commit() { asm volatile("cp.async.commit_group;"); }
template<int N>
__device__ __forceinline__ void cp_wait() { asm volatile("cp.async.wait_group %0;" :: "n"(N)); }

// ---------------- fp16 tensor-core GEMM (3-stage cp.async pipeline) ----------------
template<int OUTHALF>
__global__ void __launch_bounds__(256, 2)
k_gemm_f16(const __half* __restrict__ A, const float* __restrict__ rowscale,
           const __half* __restrict__ B, void* __restrict__ Cv, int M)
{
    constexpr int K = 256, NCOLS = 256;
    constexpr int BM = 128, BN = 128, BK = 32;
    constexpr int ALD = 40;
    constexpr int ST = 3;
    __shared__ __align__(16) __half As[ST][BM * ALD];
    __shared__ __align__(16) __half Bs[ST][BN * ALD];

    const int tid  = threadIdx.x;
    const int lane = tid & 31;
    const int warp = tid >> 5;
    const int row0 = blockIdx.y * BM;
    const int col0 = blockIdx.x * BN;
    const int warpM = (warp >> 2) * 64;
    const int warpN = (warp & 3) * 32;

    float acc[4][4][4];
#pragma unroll
    for (int i = 0; i < 4; i++)
#pragma unroll
        for (int j = 0; j < 4; j++)
#pragma unroll
            for (int r = 0; r < 4; r++) acc[i][j][r] = 0.f;

    auto stage = [&](int k0, int buf) {
#pragma unroll
        for (int i = 0; i < 2; i++) {
            int c = tid * 2 + i;
            int r = c >> 2;
            int off = (c & 3) * 8;
            int gr = row0 + r;
            if (gr >= M) gr = M - 1;
            cp16((uint32_t)__cvta_generic_to_shared(&As[buf][r * ALD + off]),
                 A + (size_t)gr * K + k0 + off);
            cp16((uint32_t)__cvta_generic_to_shared(&Bs[buf][r * ALD + off]),
                 B + (size_t)(col0 + r) * K + k0 + off);
        }
    };

    const int NT = K / BK;
    stage(0, 0);
    cp_commit();
    stage(BK, 1);
    cp_commit();

    for (int t = 0; t < NT; t++) {
        int buf = t % ST;
        if (t < NT - 1) cp_wait<1>(); else cp_wait<0>();
        __syncthreads();
        if (t + 2 < NT) {
            stage((t + 2) * BK, (t + 2) % ST);
            cp_commit();
        }

#pragma unroll
        for (int ks = 0; ks < 2; ks++) {
            const int kb = ks * 16 + (lane & 3) * 2;
            uint32_t a[4][4], b[4][2];
#pragma unroll
            for (int mi = 0; mi < 4; mi++) {
                const __half* ap = &As[buf][(warpM + mi * 16 + (lane >> 2)) * ALD + kb];
                a[mi][0] = *(const uint32_t*)ap;
                a[mi][1] = *(const uint32_t*)(ap + 8 * ALD);
                a[mi][2] = *(const uint32_t*)(ap + 8);
                a[mi][3] = *(const uint32_t*)(ap + 8 * ALD + 8);
            }
#pragma unroll
            for (int ni = 0; ni < 4; ni++) {
                const __half* bp = &Bs[buf][(warpN + ni * 8 + (lane >> 2)) * ALD + kb];
                b[ni][0] = *(const uint32_t*)bp;
                b[ni][1] = *(const uint32_t*)(bp + 8);
            }
#pragma unroll
            for (int mi = 0; mi < 4; mi++)
#pragma unroll
                for (int ni = 0; ni < 4; ni++)
                    mma_f16(acc[mi][ni], a[mi], b[ni]);
        }
    }

#pragma unroll
    for (int mi = 0; mi < 4; mi++) {
        int gr0 = row0 + warpM + mi * 16 + (lane >> 2);
        float s0 = 1.f, s1 = 1.f;
        if (rowscale) {
            if (gr0 < M)     s0 = rowscale[gr0];
            if (gr0 + 8 < M) s1 = rowscale[gr0 + 8];
        }
#pragma unroll
        for (int ni = 0; ni < 4; ni++) {
            int col = col0 + warpN + ni * 8 + (lane & 3) * 2;
            if constexpr (OUTHALF) {
                __half* Ch = (__half*)Cv;
                if (gr0 < M)
                    *(__half2*)(Ch + (size_t)gr0 * NCOLS + col) =
                        __float22half2_rn(make_float2(acc[mi][ni][0] * s0, acc[mi][ni][1] * s0));
                if (gr0 + 8 < M)
                    *(__half2*)(Ch + (size_t)(gr0 + 8) * NCOLS + col) =
                        __float22half2_rn(make_float2(acc[mi][ni][2] * s1, acc[mi][ni][3] * s1));
            } else {
                float* C = (float*)Cv;
                if (gr0 < M)
                    *(float2*)(C + (size_t)gr0 * NCOLS + col) =
                        make_float2(acc[mi][ni][0] * s0, acc[mi][ni][1] * s0);
                if (gr0 + 8 < M)
                    *(float2*)(C + (size_t)(gr0 + 8) * NCOLS + col) =
                        make_float2(acc[mi][ni][2] * s1, acc[mi][ni][3] * s1);
            }
        }
    }
}

// ---------------- stream/event singletons (host resources, created once) ----------
namespace {
struct HxRes {
    cudaStream_t s_pre = nullptr, s_g3 = nullptr, s_g2 = nullptr;
    cudaEvent_t  e_fork = nullptr, e_csr = nullptr,
                 e_g1 = nullptr, e_g3 = nullptr, e_gh1 = nullptr, e_g2 = nullptr,
                 e_zero = nullptr;
    HxRes() {
        cudaStreamCreateWithFlags(&s_pre, cudaStreamNonBlocking);
        cudaStreamCreateWithFlags(&s_g3,  cudaStreamNonBlocking);
        cudaStreamCreateWithFlags(&s_g2,  cudaStreamNonBlocking);
        cudaEventCreateWithFlags(&e_fork, cudaEventDisableTiming);
        cudaEventCreateWithFlags(&e_csr,  cudaEventDisableTiming);
        cudaEventCreateWithFlags(&e_g1,   cudaEventDisableTiming);
        cudaEventCreateWithFlags(&e_g3,   cudaEventDisableTiming);
        cudaEventCreateWithFlags(&e_gh1,  cudaEventDisableTiming);
        cudaEventCreateWithFlags(&e_g2,   cudaEventDisableTiming);
        cudaEventCreateWithFlags(&e_zero, cudaEventDisableTiming);
    }
};
HxRes g_res;
}

// ---------------- launch ----------------
extern "C" void kernel_launch(void* const* d_in, const int* in_sizes, int n_in,
                              void* d_out, int out_size)
{
    const float* features = (const float*)d_in[0];
    const float* noise    = (const float*)d_in[1];
    const float* W1       = (const float*)d_in[2];
    const float* b1       = (const float*)d_in[3];
    const float* W2       = (const float*)d_in[4];
    const float* b2       = (const float*)d_in[5];
    const float* W3       = (const float*)d_in[6];
    const float* b3       = (const float*)d_in[7];
    const float* fcW      = (const float*)d_in[8];
    const int*   src      = (const int*)d_in[9];
    const int*   dst      = (const int*)d_in[10];

    float* out     = (float*)d_out;
    float* z_out   = out;                                 // [NN, 128]
    float* h_out   = out + (size_t)NN * DOUT;             // [NN, 256]
    float* seq_out = h_out + (size_t)NN * DHID;           // [NN, 256]

    __half *pth, *phh, *pfh, *pw1, *pw23, *pfcw;
    float  *pon;
    cudaGetSymbolAddress((void**)&pth,  g_th);
    cudaGetSymbolAddress((void**)&phh,  g_hh);
    cudaGetSymbolAddress((void**)&pfh,  g_fh);
    cudaGetSymbolAddress((void**)&pw1,  g_w1h);
    cudaGetSymbolAddress((void**)&pw23, g_w23h);
    cudaGetSymbolAddress((void**)&pfcw, g_fcwh);
    cudaGetSymbolAddress((void**)&pon,  g_outnorm);

    const int T = 256;
    dim3 ggrid(2, (NN + 127) / 128);
    dim3 ggrid_lo(2, MID / 128);
    dim3 ggrid_hi(2, (NN - MID + 127) / 128);

    // ---- fork: CSR prologue on side stream ----
    cudaEventRecord(g_res.e_fork, 0);
    cudaStreamWaitEvent(g_res.s_pre, g_res.e_fork, 0);
    k_degree<<<(NE / 4 + T - 1) / T, T, 0, g_res.s_pre>>>(src, dst);
    k_scan_p1n<<<SCAN_GRID, SCAN_B, 0, g_res.s_pre>>>();
    k_scan_p3f<<<SCAN_GRID, SCAN_B, 0, g_res.s_pre>>>();
    k_csr_fill<<<(NE / 4 + T - 1) / T, T, 0, g_res.s_pre>>>(src, dst);
    cudaEventRecord(g_res.e_csr, g_res.s_pre);
    // tail: re-zero counters in the shadow of main-stream work
    k_zero_counts<<<(NN + T - 1) / T, T, 0, g_res.s_pre>>>();
    cudaEventRecord(g_res.e_zero, g_res.s_pre);

    // ---- main: all conversions in one kernel, then gemm1 ----
    k_conv_all<<<(CONV_TOTAL + T - 1) / T, T>>>(features, W1, W2, W3, fcW);
    k_gemm_f16<1><<<ggrid, T>>>(pfh, nullptr, pw1, pth, NN);
    cudaEventRecord(g_res.e_g1, 0);

    // ---- side: gemm3 (seq_fts) after gemm1, overlapping the rest ----
    cudaStreamWaitEvent(g_res.s_g3, g_res.e_g1, 0);
    k_gemm_f16<0><<<ggrid, T, 0, g_res.s_g3>>>(pfh, nullptr, pfcw, seq_out, NN);
    cudaEventRecord(g_res.e_g3, g_res.s_g3);

    // ---- main: join CSR; gather_h split into halves ----
    cudaStreamWaitEvent(0, g_res.e_csr, 0);
    k_gather_h<<<(MID * 32 + T - 1) / T, T>>>(pth, b1, h_out, phh, 0, MID);
    cudaEventRecord(g_res.e_gh1, 0);
    k_gather_h<<<((NN - MID) * 32 + T - 1) / T, T>>>(pth, b1, h_out, phh, MID, NN);

    // ---- side: gemm2 lower half overlaps gather_h upper half ----
    cudaStreamWaitEvent(g_res.s_g2, g_res.e_gh1, 0);
    k_gemm_f16<1><<<ggrid_lo, T, 0, g_res.s_g2>>>(phh, pon, pw23, pth, MID);
    cudaEventRecord(g_res.e_g2, g_res.s_g2);

    // ---- main: gemm2 upper half, join lower, gather_z ----
    k_gemm_f16<1><<<ggrid_hi, T>>>(phh + (size_t)MID * DHID, pon + MID, pw23,
                                   pth + (size_t)MID * DHID, NN - MID);
    cudaStreamWaitEvent(0, g_res.e_g2, 0);
    k_gather_z<<<(NN * 32 + T - 1) / T, T>>>(pth, b2, b3, noise, z_out);

    // ---- final joins: seq_fts + counter re-zero must complete before graph end ----
    cudaStreamWaitEvent(0, g_res.e_g3, 0);
    cudaStreamWaitEvent(0, g_res.e_zero, 0);
}